// round 16
// baseline (speedup 1.0000x reference)
#include <cuda_runtime.h>
#include <cuda_fp16.h>
#include <cstddef>

#define N_NODES 100000
#define N_EDGES 1600000
#define HDIM 128
#define CDIM 40
#define ZPAD 64    // z row padded to 64 halves (128 B)

#define SCAN_T 1024
#define SCAN_BLOCKS ((N_NODES + SCAN_T - 1) / SCAN_T)   // 98
#define CONV1KB ((N_NODES * 32 + SCAN_T - 1) / SCAN_T)  // conv blocks @1024 thr: 3125
#define K2_GRID (SCAN_BLOCKS + CONV1KB)

// ---- device scratch (allocation-free rule) ----
__device__ float  g_norm_out[N_NODES];
__device__ float  g_norm_in[N_NODES];
__device__ int    g_ints[2 * N_NODES + 128];   // [deg_out | deg_in | scan flags] (memset)
__device__ int    g_cursor[N_NODES];           // init'd by scan kernel (= off[i])
__device__ int    g_off[N_NODES + 1];
__device__ int    g_csr_src[N_EDGES];
__device__ int    g_scan_agg[SCAN_BLOCKS];
__device__ int    g_scan_pref[SCAN_BLOCKS];
__device__ float  g_bcomb[CDIM];
__device__ __half g_w1ht[HDIM * HDIM];             // W1^T fp16: [n][k]
__device__ __half g_wcombh[CDIM * HDIM];           // Wcomb^T fp16: [c][k]
__device__ __half g_xh[(size_t)N_NODES * HDIM];    // x*norm_out fp16
__device__ __half g_a1h[(size_t)N_NODES * HDIM];   // gather1 * norm_in, fp16
__device__ __half g_zh[(size_t)N_NODES * ZPAD];    // z = h1 @ Wcomb, fp16 padded

#define DEG_OUT (g_ints)
#define DEG_IN  (g_ints + N_NODES)
#define SFLAG   (g_ints + 2 * N_NODES)

#define APAD 136   // halves per smem row (uint4-aligned, conflict-free frags)

// ---------------------------------------------------------------------------
// K1: degree histogram + independent weight prep (W1^T fp16, Wcomb^T fp16, bcomb)
#define DEGB   ((N_EDGES + 255) / 256)         // 6250
#define W1T_B  ((HDIM * HDIM) / 256)           // 64
#define WC_B   (HDIM + 1)                      // 129
#define K1_GRID (DEGB + W1T_B + WC_B)

__global__ void __launch_bounds__(256)
deg_prep_kernel(const int* __restrict__ src, const int* __restrict__ dst,
                const float* __restrict__ W1,
                const float* __restrict__ W2, const float* __restrict__ Wfc,
                const float* __restrict__ b2, const float* __restrict__ bfc) {
    const int bid = blockIdx.x;
    const int tid = threadIdx.x;
    if (bid < DEGB) {
        int e = bid * 256 + tid;
        if (e < N_EDGES) {
            atomicAdd(&DEG_OUT[src[e]], 1);
            atomicAdd(&DEG_IN[dst[e]], 1);
        }
    } else if (bid < DEGB + W1T_B) {
        int idx = (bid - DEGB) * 256 + tid;              // over 16384 elems
        int k = idx >> 7;
        int n = idx & 127;
        g_w1ht[n * HDIM + k] = __float2half_rn(W1[k * HDIM + n]);
    } else {
        int j = bid - DEGB - W1T_B;                      // 0..128; j<128: row j of W2
        __shared__ float row[HDIM];
        const float* srcrow = (j < HDIM) ? (W2 + j * HDIM) : b2;
        if (tid < HDIM) row[tid] = srcrow[tid];
        __syncthreads();
        if (tid < CDIM) {
            float acc = (j < HDIM) ? 0.f : bfc[tid];
#pragma unroll 8
            for (int k = 0; k < HDIM; k++)
                acc = fmaf(row[k], Wfc[k * CDIM + tid], acc);
            if (j < HDIM) g_wcombh[tid * HDIM + j] = __float2half_rn(acc);
            else          g_bcomb[tid] = acc;
        }
    }
}

// ---------------------------------------------------------------------------
// K2: lookback scan of deg_in -> g_off + cursor(=off) + norms (blocks 0..97),
//     AND x*norm_out -> fp16 conversion (blocks 98..; needs only deg_out).
__global__ void __launch_bounds__(SCAN_T)
scan_norm_conv_kernel(const float* __restrict__ x) {
    const int b = blockIdx.x;
    const int tid = threadIdx.x;

    if (b >= SCAN_BLOCKS) {
        // ---- conversion branch: xh = fp16(x * rsqrt(max(deg_out,1))) ----
        int t = (b - SCAN_BLOCKS) * SCAN_T + tid;
        int node = t >> 5;
        int lane = t & 31;
        if (node < N_NODES) {
            float4 v = __ldg((const float4*)x + (size_t)node * 32 + lane);
            float no = rsqrtf(fmaxf((float)DEG_OUT[node], 1.0f));
            __half2 p0 = __floats2half2_rn(v.x * no, v.y * no);
            __half2 p1 = __floats2half2_rn(v.z * no, v.w * no);
            uint2 w;
            w.x = *reinterpret_cast<unsigned*>(&p0);
            w.y = *reinterpret_cast<unsigned*>(&p1);
            ((uint2*)g_xh)[(size_t)node * 32 + lane] = w;
        }
        return;
    }

    // ---- scan + norm branch ----
    __shared__ int sm[SCAN_T];
    __shared__ int s_prefix;
    const int i = b * SCAN_T + tid;

    int v = (i < N_NODES) ? DEG_IN[i] : 0;
    if (i < N_NODES) {
        g_norm_out[i] = rsqrtf(fmaxf((float)DEG_OUT[i], 1.0f));
        g_norm_in[i]  = rsqrtf(fmaxf((float)v, 1.0f));
    }
    sm[tid] = v;
    __syncthreads();
    for (int ofs = 1; ofs < SCAN_T; ofs <<= 1) {
        int t2 = (tid >= ofs) ? sm[tid - ofs] : 0;
        __syncthreads();
        sm[tid] += t2;
        __syncthreads();
    }

    if (tid == 0) {
        int total = sm[SCAN_T - 1];
        g_scan_agg[b] = total;
        __threadfence();
        atomicExch(&SFLAG[b], 1);

        int p = 0;
        for (int j = b - 1; j >= 0; --j) {
            int f;
            do { f = atomicAdd(&SFLAG[j], 0); } while (f == 0);
            __threadfence();
            if (f == 2) { p += g_scan_pref[j]; break; }
            p += g_scan_agg[j];
        }
        g_scan_pref[b] = p + total;
        __threadfence();
        atomicExch(&SFLAG[b], 2);
        s_prefix = p;
    }
    __syncthreads();

    if (i < N_NODES) {
        int inc = sm[tid] + s_prefix;      // inclusive prefix
        g_off[i + 1]  = inc;
        g_cursor[i]   = inc - v;           // exclusive prefix = off[i]
    }
    if (i == 0) g_off[0] = 0;
}

// ---------------------------------------------------------------------------
// K3: CSR fill, 2 edges per thread; cursor holds off[d] so one atomic suffices
#define FILL_B ((N_EDGES + 511) / 512)   // 3125

__global__ void __launch_bounds__(256)
fill_kernel(const int* __restrict__ src, const int* __restrict__ dst) {
    int e0 = blockIdx.x * 512 + threadIdx.x;
    int e1 = e0 + 256;
    if (e0 < N_EDGES) {
        int d = dst[e0];
        int pos = atomicAdd(&g_cursor[d], 1);
        g_csr_src[pos] = src[e0];
    }
    if (e1 < N_EDGES) {
        int d = dst[e1];
        int pos = atomicAdd(&g_cursor[d], 1);
        g_csr_src[pos] = src[e1];
    }
}

// ---------------------------------------------------------------------------
// helpers
__device__ __forceinline__ __half2 u2h2(unsigned u) {
    return *reinterpret_cast<__half2*>(&u);
}

__device__ __forceinline__ void acc_u4(const uint4& r, float4& a, float4& b) {
    float2 f0 = __half22float2(u2h2(r.x));
    float2 f1 = __half22float2(u2h2(r.y));
    float2 f2 = __half22float2(u2h2(r.z));
    float2 f3 = __half22float2(u2h2(r.w));
    a.x += f0.x; a.y += f0.y; a.z += f1.x; a.w += f1.y;
    b.x += f2.x; b.y += f2.y; b.z += f3.x; b.w += f3.y;
}

__device__ __forceinline__ void acc_u2(const uint2& r, float4& a) {
    float2 f0 = __half22float2(u2h2(r.x));
    float2 f1 = __half22float2(u2h2(r.y));
    a.x += f0.x; a.y += f0.y; a.z += f1.x; a.w += f1.y;
}

// ---------------------------------------------------------------------------
// K4 (PROFILED): gather1, 2 nodes per warp (16 lanes x uint4 per node):
//   a1h[n,:] = fp16( norm_in[n] * sum_{s in N_in(n)} xh[s,:] )
__global__ void __launch_bounds__(256)
gather1_kernel() {
    int t    = blockIdx.x * blockDim.x + threadIdx.x;
    int lane = t & 31;
    int half = lane >> 4;
    int hl   = lane & 15;
    int node = (t >> 5) * 2 + half;

    int beg = 0, end = 0;
    if (node < N_NODES) { beg = g_off[node]; end = g_off[node + 1]; }

    const uint4* in = (const uint4*)g_xh;     // 16 uint4 per 128-half row

    float4 accA = make_float4(0.f, 0.f, 0.f, 0.f);
    float4 accB = make_float4(0.f, 0.f, 0.f, 0.f);

    int j = beg;
    for (; j + 4 <= end; j += 4) {
        int s0 = g_csr_src[j + 0];
        int s1 = g_csr_src[j + 1];
        int s2 = g_csr_src[j + 2];
        int s3 = g_csr_src[j + 3];
        uint4 r0 = __ldg(in + (size_t)s0 * 16 + hl);
        uint4 r1 = __ldg(in + (size_t)s1 * 16 + hl);
        uint4 r2 = __ldg(in + (size_t)s2 * 16 + hl);
        uint4 r3 = __ldg(in + (size_t)s3 * 16 + hl);
        uint4 p, q;
        *(__half2*)&p.x = __hadd2(u2h2(r0.x), u2h2(r1.x));
        *(__half2*)&p.y = __hadd2(u2h2(r0.y), u2h2(r1.y));
        *(__half2*)&p.z = __hadd2(u2h2(r0.z), u2h2(r1.z));
        *(__half2*)&p.w = __hadd2(u2h2(r0.w), u2h2(r1.w));
        *(__half2*)&q.x = __hadd2(u2h2(r2.x), u2h2(r3.x));
        *(__half2*)&q.y = __hadd2(u2h2(r2.y), u2h2(r3.y));
        *(__half2*)&q.z = __hadd2(u2h2(r2.z), u2h2(r3.z));
        *(__half2*)&q.w = __hadd2(u2h2(r2.w), u2h2(r3.w));
        acc_u4(p, accA, accB);
        acc_u4(q, accA, accB);
    }
    for (; j < end; j++) {
        uint4 r = __ldg(in + (size_t)g_csr_src[j] * 16 + hl);
        acc_u4(r, accA, accB);
    }

    if (node < N_NODES) {
        float ni = g_norm_in[node];
        __half2 h0 = __floats2half2_rn(accA.x * ni, accA.y * ni);
        __half2 h1 = __floats2half2_rn(accA.z * ni, accA.w * ni);
        __half2 h2 = __floats2half2_rn(accB.x * ni, accB.y * ni);
        __half2 h3 = __floats2half2_rn(accB.z * ni, accB.w * ni);
        uint4 w;
        w.x = *reinterpret_cast<unsigned*>(&h0);
        w.y = *reinterpret_cast<unsigned*>(&h1);
        w.z = *reinterpret_cast<unsigned*>(&h2);
        w.w = *reinterpret_cast<unsigned*>(&h3);
        ((uint4*)g_a1h)[(size_t)node * 16 + hl] = w;
    }
}

// ---------------------------------------------------------------------------
// K5: fused HMMA GEMM + z-GEMM.  Wcomb is NOT staged in smem — the z-MMA reads
// its fragments via __ldg (10 KB, L1-resident) -> smem 69.6 KB -> 3 blocks/SM.
#define GEMM_SMEM (2 * HDIM * APAD * (int)sizeof(__half))   // 69632 B

__global__ void __launch_bounds__(256)
gemm_fused_kernel(const float* __restrict__ bias) {
    extern __shared__ __half smem[];
    __half* As = smem;                          // [128][APAD]
    __half* Ws = smem + HDIM * APAD;            // [128][APAD]  (W1^T: [n][k])
    __shared__ float bs[HDIM];

    const int tid = threadIdx.x;
    const int block_row = blockIdx.x * 128;

    if (tid < HDIM) bs[tid] = bias[tid];

#pragma unroll
    for (int t = 0; t < 8; t++) {
        int idx = tid + t * 256;
        int r   = idx >> 4;
        int c8  = (idx & 15) << 3;
        int n   = block_row + r;
        uint4 v = make_uint4(0u, 0u, 0u, 0u);
        if (n < N_NODES) v = *(const uint4*)(g_a1h + (size_t)n * HDIM + c8);
        *(uint4*)(As + r * APAD + c8) = v;
        *(uint4*)(Ws + r * APAD + c8) = *(const uint4*)(g_w1ht + r * HDIM + c8);
    }
    __syncthreads();

    const int warp  = tid >> 5;
    const int lane  = tid & 31;
    const int warpM = warp & 3;
    const int warpN = warp >> 2;
    const int lr    = lane >> 2;
    const int lc    = (lane & 3) << 1;

    float acc[2][8][4];
#pragma unroll
    for (int m = 0; m < 2; m++)
#pragma unroll
        for (int n = 0; n < 8; n++)
#pragma unroll
            for (int q = 0; q < 4; q++) acc[m][n][q] = 0.f;

#pragma unroll
    for (int k16 = 0; k16 < 8; k16++) {
        const int kb = k16 * 16 + lc;
        unsigned a[2][4];
#pragma unroll
        for (int m = 0; m < 2; m++) {
            const __half* ap = As + (warpM * 32 + m * 16 + lr) * APAD;
            a[m][0] = *(const unsigned*)(ap + kb);
            a[m][1] = *(const unsigned*)(ap + 8 * APAD + kb);
            a[m][2] = *(const unsigned*)(ap + kb + 8);
            a[m][3] = *(const unsigned*)(ap + 8 * APAD + kb + 8);
        }
#pragma unroll
        for (int n = 0; n < 8; n++) {
            const __half* bp = Ws + (warpN * 64 + n * 8 + lr) * APAD + kb;
            unsigned b0 = *(const unsigned*)(bp);
            unsigned b1 = *(const unsigned*)(bp + 8);
#pragma unroll
            for (int m = 0; m < 2; m++) {
                asm volatile(
                    "mma.sync.aligned.m16n8k16.row.col.f32.f16.f16.f32 "
                    "{%0,%1,%2,%3}, {%4,%5,%6,%7}, {%8,%9}, {%0,%1,%2,%3};"
                    : "+f"(acc[m][n][0]), "+f"(acc[m][n][1]),
                      "+f"(acc[m][n][2]), "+f"(acc[m][n][3])
                    : "r"(a[m][0]), "r"(a[m][1]), "r"(a[m][2]), "r"(a[m][3]),
                      "r"(b0), "r"(b1));
            }
        }
    }

    // epilogue 1: h1 = relu(acc + bias) * norm_out, written back into As (fp16)
    __syncthreads();
#pragma unroll
    for (int m = 0; m < 2; m++) {
        int r0 = block_row + warpM * 32 + m * 16 + lr;
        int r1 = r0 + 8;
        float no0 = (r0 < N_NODES) ? g_norm_out[r0] : 0.f;
        float no1 = (r1 < N_NODES) ? g_norm_out[r1] : 0.f;
        int sr0 = warpM * 32 + m * 16 + lr;
#pragma unroll
        for (int n = 0; n < 8; n++) {
            int col = warpN * 64 + n * 8 + lc;
            float bb0 = bs[col], bb1 = bs[col + 1];
            __half2 h0 = __floats2half2_rn(fmaxf(acc[m][n][0] + bb0, 0.f) * no0,
                                           fmaxf(acc[m][n][1] + bb1, 0.f) * no0);
            __half2 h1 = __floats2half2_rn(fmaxf(acc[m][n][2] + bb0, 0.f) * no1,
                                           fmaxf(acc[m][n][3] + bb1, 0.f) * no1);
            *(__half2*)(As + sr0 * APAD + col)       = h0;
            *(__half2*)(As + (sr0 + 8) * APAD + col) = h1;
        }
    }
    __syncthreads();

    // second MMA: z = h1 @ Wcomb; B-fragments read straight from global (L1-hot)
    float zacc[5][4];
#pragma unroll
    for (int n = 0; n < 5; n++)
#pragma unroll
        for (int q = 0; q < 4; q++) zacc[n][q] = 0.f;

#pragma unroll
    for (int k16 = 0; k16 < 8; k16++) {
        const int kb = k16 * 16 + lc;
        const __half* ap = As + (warp * 16 + lr) * APAD;
        unsigned a0 = *(const unsigned*)(ap + kb);
        unsigned a1 = *(const unsigned*)(ap + 8 * APAD + kb);
        unsigned a2 = *(const unsigned*)(ap + kb + 8);
        unsigned a3 = *(const unsigned*)(ap + 8 * APAD + kb + 8);
#pragma unroll
        for (int n = 0; n < 5; n++) {
            const __half* wrow = g_wcombh + (n * 8 + lr) * HDIM + kb;
            unsigned b0 = __ldg((const unsigned*)wrow);
            unsigned b1 = __ldg((const unsigned*)(wrow + 8));
            asm volatile(
                "mma.sync.aligned.m16n8k16.row.col.f32.f16.f16.f32 "
                "{%0,%1,%2,%3}, {%4,%5,%6,%7}, {%8,%9}, {%0,%1,%2,%3};"
                : "+f"(zacc[n][0]), "+f"(zacc[n][1]), "+f"(zacc[n][2]), "+f"(zacc[n][3])
                : "r"(a0), "r"(a1), "r"(a2), "r"(a3), "r"(b0), "r"(b1));
        }
    }

    // epilogue 2: write z fp16 (padded) + zero cols 40..63
    int r0 = block_row + warp * 16 + lr;
    int r1 = r0 + 8;
#pragma unroll
    for (int n = 0; n < 5; n++) {
        int col = n * 8 + lc;
        if (r0 < N_NODES) {
            __half2 h = __floats2half2_rn(zacc[n][0], zacc[n][1]);
            *(__half2*)(g_zh + (size_t)r0 * ZPAD + col) = h;
        }
        if (r1 < N_NODES) {
            __half2 h = __floats2half2_rn(zacc[n][2], zacc[n][3]);
            *(__half2*)(g_zh + (size_t)r1 * ZPAD + col) = h;
        }
    }
#pragma unroll
    for (int n = 5; n < 8; n++) {
        int col = n * 8 + lc;
        if (r0 < N_NODES) *(unsigned*)(g_zh + (size_t)r0 * ZPAD + col) = 0u;
        if (r1 < N_NODES) *(unsigned*)(g_zh + (size_t)r1 * ZPAD + col) = 0u;
    }
}

// ---------------------------------------------------------------------------
// K6: gather2, 2 nodes per warp (16 lanes x uint2 over 64-half padded z row):
//   out[n, c] = norm_in[n] * sum_{s in N_in(n)} z[s, c] + bcomb[c]
__global__ void __launch_bounds__(256)
gather2_out_kernel(float* __restrict__ out) {
    int t    = blockIdx.x * blockDim.x + threadIdx.x;
    int lane = t & 31;
    int half = lane >> 4;
    int hl   = lane & 15;
    int node = (t >> 5) * 2 + half;

    int beg = 0, end = 0;
    if (node < N_NODES) { beg = g_off[node]; end = g_off[node + 1]; }

    const uint2* z2 = (const uint2*)g_zh;   // 16 uint2 per padded row

    float4 acc = make_float4(0.f, 0.f, 0.f, 0.f);
    int j = beg;
    for (; j + 4 <= end; j += 4) {
        int s0 = g_csr_src[j + 0];
        int s1 = g_csr_src[j + 1];
        int s2 = g_csr_src[j + 2];
        int s3 = g_csr_src[j + 3];
        uint2 r0 = __ldg(z2 + (size_t)s0 * 16 + hl);
        uint2 r1 = __ldg(z2 + (size_t)s1 * 16 + hl);
        uint2 r2 = __ldg(z2 + (size_t)s2 * 16 + hl);
        uint2 r3 = __ldg(z2 + (size_t)s3 * 16 + hl);
        uint2 p, q;
        *(__half2*)&p.x = __hadd2(u2h2(r0.x), u2h2(r1.x));
        *(__half2*)&p.y = __hadd2(u2h2(r0.y), u2h2(r1.y));
        *(__half2*)&q.x = __hadd2(u2h2(r2.x), u2h2(r3.x));
        *(__half2*)&q.y = __hadd2(u2h2(r2.y), u2h2(r3.y));
        acc_u2(p, acc);
        acc_u2(q, acc);
    }
    for (; j < end; j++) {
        uint2 r = __ldg(z2 + (size_t)g_csr_src[j] * 16 + hl);
        acc_u2(r, acc);
    }

    if (node < N_NODES && hl < 10) {   // 10 lanes x 4 floats = 40 output cols
        float ni = g_norm_in[node];
        float4 b = *(const float4*)(g_bcomb + hl * 4);
        float4 v = make_float4(fmaf(acc.x, ni, b.x), fmaf(acc.y, ni, b.y),
                               fmaf(acc.z, ni, b.z), fmaf(acc.w, ni, b.w));
        *(float4*)(out + (size_t)node * CDIM + hl * 4) = v;
    }
}

// ---------------------------------------------------------------------------
extern "C" void kernel_launch(void* const* d_in, const int* in_sizes, int n_in,
                              void* d_out, int out_size) {
    const float* x   = (const float*)d_in[0];
    const int*   ei  = (const int*)  d_in[1];
    const float* W1  = (const float*)d_in[2];
    const float* b1  = (const float*)d_in[3];
    const float* W2  = (const float*)d_in[4];
    const float* b2  = (const float*)d_in[5];
    const float* Wfc = (const float*)d_in[6];
    const float* bfc = (const float*)d_in[7];
    float* out = (float*)d_out;

    const int* src = ei;            // edge_index row 0
    const int* dst = ei + N_EDGES;  // edge_index row 1

    int* p_ints;
    cudaGetSymbolAddress((void**)&p_ints, g_ints);

    static bool attr_set = false;
    if (!attr_set) {
        cudaFuncSetAttribute(gemm_fused_kernel,
                             cudaFuncAttributeMaxDynamicSharedMemorySize, GEMM_SMEM);
        attr_set = true;
    }

    const int pair_blocks = ((N_NODES + 1) / 2 * 32 + 255) / 256;  // 6250
    const int node_blocks = (N_NODES + 127) / 128;                 // 782

    // zero [deg_out | deg_in | scan flags]  (cursor written by scan kernel)
    cudaMemsetAsync(p_ints, 0, (2 * N_NODES + 128) * sizeof(int));
    // K1: degrees + weight prep (independent of norms)
    deg_prep_kernel<<<K1_GRID, 256>>>(src, dst, W1, W2, Wfc, b2, bfc);
    // K2: lookback scan + norms + cursor init + x*norm_out->fp16
    scan_norm_conv_kernel<<<K2_GRID, SCAN_T>>>(x);
    // K3: CSR fill (single atomic per edge, 2 edges/thread)
    fill_kernel<<<FILL_B, 256>>>(src, dst);
    // K4 (profiled): gather1, 2 nodes/warp -> a1h
    gather1_kernel<<<pair_blocks, 256>>>();
    // K5: fused GEMM (h1 in smem) + z-GEMM (Wcomb via L1) -> zh
    gemm_fused_kernel<<<node_blocks, 256, GEMM_SMEM>>>(b1);
    // K6: gather2, 2 nodes/warp on 40-dim z rows -> out
    gather2_out_kernel<<<pair_blocks, 256>>>(out);
}

// round 17
// speedup vs baseline: 1.0765x; 1.0765x over previous
#include <cuda_runtime.h>
#include <cuda_fp16.h>
#include <cstddef>

#define N_NODES 100000
#define N_EDGES 1600000
#define HDIM 128
#define CDIM 40
#define ZPAD 64    // z row padded to 64 halves (128 B)

#define SCAN_T 1024
#define SCAN_BLOCKS ((N_NODES + SCAN_T - 1) / SCAN_T)   // 98
#define CONV1KB ((N_NODES * 32 + SCAN_T - 1) / SCAN_T)  // conv blocks @1024 thr: 3125
#define K2_GRID (SCAN_BLOCKS + CONV1KB)

// ---- device scratch (allocation-free rule) ----
__device__ float  g_norm_out[N_NODES];
__device__ float  g_norm_in[N_NODES];
__device__ int    g_ints[2 * N_NODES + 128];   // [deg_out | deg_in | scan flags] (memset)
__device__ int    g_cursor[N_NODES];           // init'd by scan kernel (= off[i])
__device__ int    g_off[N_NODES + 1];
__device__ int    g_csr_src[N_EDGES];
__device__ int    g_scan_agg[SCAN_BLOCKS];
__device__ int    g_scan_pref[SCAN_BLOCKS];
__device__ float  g_bcomb[CDIM];
__device__ __half g_w1ht[HDIM * HDIM];             // W1^T fp16: [n][k]
__device__ __half g_wcombh[CDIM * HDIM];           // Wcomb^T fp16: [c][k]
__device__ __half g_xh[(size_t)N_NODES * HDIM];    // x*norm_out fp16
__device__ __half g_a1h[(size_t)N_NODES * HDIM];   // gather1 * norm_in, fp16
__device__ __half g_zh[(size_t)N_NODES * ZPAD];    // z = h1 @ Wcomb, fp16 padded

#define DEG_OUT (g_ints)
#define DEG_IN  (g_ints + N_NODES)
#define SFLAG   (g_ints + 2 * N_NODES)

#define APAD 136   // halves per smem row (uint4-aligned, conflict-free frags)

// ---------------------------------------------------------------------------
// K1: degree histogram + independent weight prep (W1^T fp16, Wcomb^T fp16, bcomb)
#define DEGB   ((N_EDGES + 255) / 256)         // 6250
#define W1T_B  ((HDIM * HDIM) / 256)           // 64
#define WC_B   (HDIM + 1)                      // 129
#define K1_GRID (DEGB + W1T_B + WC_B)

__global__ void __launch_bounds__(256)
deg_prep_kernel(const int* __restrict__ src, const int* __restrict__ dst,
                const float* __restrict__ W1,
                const float* __restrict__ W2, const float* __restrict__ Wfc,
                const float* __restrict__ b2, const float* __restrict__ bfc) {
    const int bid = blockIdx.x;
    const int tid = threadIdx.x;
    if (bid < DEGB) {
        int e = bid * 256 + tid;
        if (e < N_EDGES) {
            atomicAdd(&DEG_OUT[src[e]], 1);
            atomicAdd(&DEG_IN[dst[e]], 1);
        }
    } else if (bid < DEGB + W1T_B) {
        int idx = (bid - DEGB) * 256 + tid;              // over 16384 elems
        int k = idx >> 7;
        int n = idx & 127;
        g_w1ht[n * HDIM + k] = __float2half_rn(W1[k * HDIM + n]);
    } else {
        int j = bid - DEGB - W1T_B;                      // 0..128; j<128: row j of W2
        __shared__ float row[HDIM];
        const float* srcrow = (j < HDIM) ? (W2 + j * HDIM) : b2;
        if (tid < HDIM) row[tid] = srcrow[tid];
        __syncthreads();
        if (tid < CDIM) {
            float acc = (j < HDIM) ? 0.f : bfc[tid];
#pragma unroll 8
            for (int k = 0; k < HDIM; k++)
                acc = fmaf(row[k], Wfc[k * CDIM + tid], acc);
            if (j < HDIM) g_wcombh[tid * HDIM + j] = __float2half_rn(acc);
            else          g_bcomb[tid] = acc;
        }
    }
}

// ---------------------------------------------------------------------------
// K2: lookback scan of deg_in -> g_off + cursor(=off) + norms (blocks 0..97),
//     AND x*norm_out -> fp16 conversion (blocks 98..; needs only deg_out).
__global__ void __launch_bounds__(SCAN_T)
scan_norm_conv_kernel(const float* __restrict__ x) {
    const int b = blockIdx.x;
    const int tid = threadIdx.x;

    if (b >= SCAN_BLOCKS) {
        // ---- conversion branch: xh = fp16(x * rsqrt(max(deg_out,1))) ----
        int t = (b - SCAN_BLOCKS) * SCAN_T + tid;
        int node = t >> 5;
        int lane = t & 31;
        if (node < N_NODES) {
            float4 v = __ldg((const float4*)x + (size_t)node * 32 + lane);
            float no = rsqrtf(fmaxf((float)DEG_OUT[node], 1.0f));
            __half2 p0 = __floats2half2_rn(v.x * no, v.y * no);
            __half2 p1 = __floats2half2_rn(v.z * no, v.w * no);
            uint2 w;
            w.x = *reinterpret_cast<unsigned*>(&p0);
            w.y = *reinterpret_cast<unsigned*>(&p1);
            ((uint2*)g_xh)[(size_t)node * 32 + lane] = w;
        }
        return;
    }

    // ---- scan + norm branch ----
    __shared__ int sm[SCAN_T];
    __shared__ int s_prefix;
    const int i = b * SCAN_T + tid;

    int v = (i < N_NODES) ? DEG_IN[i] : 0;
    if (i < N_NODES) {
        g_norm_out[i] = rsqrtf(fmaxf((float)DEG_OUT[i], 1.0f));
        g_norm_in[i]  = rsqrtf(fmaxf((float)v, 1.0f));
    }
    sm[tid] = v;
    __syncthreads();
    for (int ofs = 1; ofs < SCAN_T; ofs <<= 1) {
        int t2 = (tid >= ofs) ? sm[tid - ofs] : 0;
        __syncthreads();
        sm[tid] += t2;
        __syncthreads();
    }

    if (tid == 0) {
        int total = sm[SCAN_T - 1];
        g_scan_agg[b] = total;
        __threadfence();
        atomicExch(&SFLAG[b], 1);

        int p = 0;
        for (int j = b - 1; j >= 0; --j) {
            int f;
            do { f = atomicAdd(&SFLAG[j], 0); } while (f == 0);
            __threadfence();
            if (f == 2) { p += g_scan_pref[j]; break; }
            p += g_scan_agg[j];
        }
        g_scan_pref[b] = p + total;
        __threadfence();
        atomicExch(&SFLAG[b], 2);
        s_prefix = p;
    }
    __syncthreads();

    if (i < N_NODES) {
        int inc = sm[tid] + s_prefix;      // inclusive prefix
        g_off[i + 1]  = inc;
        g_cursor[i]   = inc - v;           // exclusive prefix = off[i]
    }
    if (i == 0) g_off[0] = 0;
}

// ---------------------------------------------------------------------------
// K3: CSR fill; cursor holds off[d] so a single atomic yields the position
__global__ void __launch_bounds__(256)
fill_kernel(const int* __restrict__ src, const int* __restrict__ dst) {
    int e = blockIdx.x * blockDim.x + threadIdx.x;
    if (e < N_EDGES) {
        int d = dst[e];
        int pos = atomicAdd(&g_cursor[d], 1);
        g_csr_src[pos] = src[e];
    }
}

// ---------------------------------------------------------------------------
// helpers
__device__ __forceinline__ __half2 u2h2(unsigned u) {
    return *reinterpret_cast<__half2*>(&u);
}

__device__ __forceinline__ void acc_u4(const uint4& r, float4& a, float4& b) {
    float2 f0 = __half22float2(u2h2(r.x));
    float2 f1 = __half22float2(u2h2(r.y));
    float2 f2 = __half22float2(u2h2(r.z));
    float2 f3 = __half22float2(u2h2(r.w));
    a.x += f0.x; a.y += f0.y; a.z += f1.x; a.w += f1.y;
    b.x += f2.x; b.y += f2.y; b.z += f3.x; b.w += f3.y;
}

__device__ __forceinline__ void acc_u2(const uint2& r, float4& a) {
    float2 f0 = __half22float2(u2h2(r.x));
    float2 f1 = __half22float2(u2h2(r.y));
    a.x += f0.x; a.y += f0.y; a.z += f1.x; a.w += f1.y;
}

// ---------------------------------------------------------------------------
// K4 (PROFILED): gather1, 2 nodes per warp (16 lanes x uint4 per node):
//   a1h[n,:] = fp16( norm_in[n] * sum_{s in N_in(n)} xh[s,:] )
__global__ void __launch_bounds__(256)
gather1_kernel() {
    int t    = blockIdx.x * blockDim.x + threadIdx.x;
    int lane = t & 31;
    int half = lane >> 4;
    int hl   = lane & 15;
    int node = (t >> 5) * 2 + half;

    int beg = 0, end = 0;
    if (node < N_NODES) { beg = g_off[node]; end = g_off[node + 1]; }

    const uint4* in = (const uint4*)g_xh;     // 16 uint4 per 128-half row

    float4 accA = make_float4(0.f, 0.f, 0.f, 0.f);
    float4 accB = make_float4(0.f, 0.f, 0.f, 0.f);

    int j = beg;
    for (; j + 4 <= end; j += 4) {
        int s0 = g_csr_src[j + 0];
        int s1 = g_csr_src[j + 1];
        int s2 = g_csr_src[j + 2];
        int s3 = g_csr_src[j + 3];
        uint4 r0 = __ldg(in + (size_t)s0 * 16 + hl);
        uint4 r1 = __ldg(in + (size_t)s1 * 16 + hl);
        uint4 r2 = __ldg(in + (size_t)s2 * 16 + hl);
        uint4 r3 = __ldg(in + (size_t)s3 * 16 + hl);
        uint4 p, q;
        *(__half2*)&p.x = __hadd2(u2h2(r0.x), u2h2(r1.x));
        *(__half2*)&p.y = __hadd2(u2h2(r0.y), u2h2(r1.y));
        *(__half2*)&p.z = __hadd2(u2h2(r0.z), u2h2(r1.z));
        *(__half2*)&p.w = __hadd2(u2h2(r0.w), u2h2(r1.w));
        *(__half2*)&q.x = __hadd2(u2h2(r2.x), u2h2(r3.x));
        *(__half2*)&q.y = __hadd2(u2h2(r2.y), u2h2(r3.y));
        *(__half2*)&q.z = __hadd2(u2h2(r2.z), u2h2(r3.z));
        *(__half2*)&q.w = __hadd2(u2h2(r2.w), u2h2(r3.w));
        acc_u4(p, accA, accB);
        acc_u4(q, accA, accB);
    }
    for (; j < end; j++) {
        uint4 r = __ldg(in + (size_t)g_csr_src[j] * 16 + hl);
        acc_u4(r, accA, accB);
    }

    if (node < N_NODES) {
        float ni = g_norm_in[node];
        __half2 h0 = __floats2half2_rn(accA.x * ni, accA.y * ni);
        __half2 h1 = __floats2half2_rn(accA.z * ni, accA.w * ni);
        __half2 h2 = __floats2half2_rn(accB.x * ni, accB.y * ni);
        __half2 h3 = __floats2half2_rn(accB.z * ni, accB.w * ni);
        uint4 w;
        w.x = *reinterpret_cast<unsigned*>(&h0);
        w.y = *reinterpret_cast<unsigned*>(&h1);
        w.z = *reinterpret_cast<unsigned*>(&h2);
        w.w = *reinterpret_cast<unsigned*>(&h3);
        ((uint4*)g_a1h)[(size_t)node * 16 + hl] = w;
    }
}

// ---------------------------------------------------------------------------
// K5: fused HMMA GEMM + z-GEMM (R15 config: Wcomb staged in smem):
//   h1 = relu(a1h @ W1 + b1) * norm_out      (fp16, written back into smem A)
//   zh[n, 0:40] = h1[n,:] @ Wcomb            (fp16 padded row, cols 40..63 = 0)
#define GEMM_SMEM ((2 * HDIM + CDIM) * APAD * (int)sizeof(__half))

__global__ void __launch_bounds__(256)
gemm_fused_kernel(const float* __restrict__ bias) {
    extern __shared__ __half smem[];
    __half* As = smem;                          // [128][APAD]
    __half* Ws = smem + HDIM * APAD;            // [128][APAD]  (W1^T: [n][k])
    __half* Wc = smem + 2 * HDIM * APAD;        // [40][APAD]   (Wcomb^T: [c][k])
    __shared__ float bs[HDIM];

    const int tid = threadIdx.x;
    const int block_row = blockIdx.x * 128;

    if (tid < HDIM) bs[tid] = bias[tid];

#pragma unroll
    for (int t = 0; t < 8; t++) {
        int idx = tid + t * 256;
        int r   = idx >> 4;
        int c8  = (idx & 15) << 3;
        int n   = block_row + r;
        uint4 v = make_uint4(0u, 0u, 0u, 0u);
        if (n < N_NODES) v = *(const uint4*)(g_a1h + (size_t)n * HDIM + c8);
        *(uint4*)(As + r * APAD + c8) = v;
        *(uint4*)(Ws + r * APAD + c8) = *(const uint4*)(g_w1ht + r * HDIM + c8);
    }
    for (int idx = tid; idx < (CDIM * HDIM) / 8; idx += 256) {
        int r  = idx >> 4;
        int c8 = (idx & 15) << 3;
        *(uint4*)(Wc + r * APAD + c8) = ((const uint4*)g_wcombh)[idx];
    }
    __syncthreads();

    const int warp  = tid >> 5;
    const int lane  = tid & 31;
    const int warpM = warp & 3;
    const int warpN = warp >> 2;
    const int lr    = lane >> 2;
    const int lc    = (lane & 3) << 1;

    float acc[2][8][4];
#pragma unroll
    for (int m = 0; m < 2; m++)
#pragma unroll
        for (int n = 0; n < 8; n++)
#pragma unroll
            for (int q = 0; q < 4; q++) acc[m][n][q] = 0.f;

#pragma unroll
    for (int k16 = 0; k16 < 8; k16++) {
        const int kb = k16 * 16 + lc;
        unsigned a[2][4];
#pragma unroll
        for (int m = 0; m < 2; m++) {
            const __half* ap = As + (warpM * 32 + m * 16 + lr) * APAD;
            a[m][0] = *(const unsigned*)(ap + kb);
            a[m][1] = *(const unsigned*)(ap + 8 * APAD + kb);
            a[m][2] = *(const unsigned*)(ap + kb + 8);
            a[m][3] = *(const unsigned*)(ap + 8 * APAD + kb + 8);
        }
#pragma unroll
        for (int n = 0; n < 8; n++) {
            const __half* bp = Ws + (warpN * 64 + n * 8 + lr) * APAD + kb;
            unsigned b0 = *(const unsigned*)(bp);
            unsigned b1 = *(const unsigned*)(bp + 8);
#pragma unroll
            for (int m = 0; m < 2; m++) {
                asm volatile(
                    "mma.sync.aligned.m16n8k16.row.col.f32.f16.f16.f32 "
                    "{%0,%1,%2,%3}, {%4,%5,%6,%7}, {%8,%9}, {%0,%1,%2,%3};"
                    : "+f"(acc[m][n][0]), "+f"(acc[m][n][1]),
                      "+f"(acc[m][n][2]), "+f"(acc[m][n][3])
                    : "r"(a[m][0]), "r"(a[m][1]), "r"(a[m][2]), "r"(a[m][3]),
                      "r"(b0), "r"(b1));
            }
        }
    }

    // epilogue 1: h1 = relu(acc + bias) * norm_out, written back into As (fp16)
    __syncthreads();
#pragma unroll
    for (int m = 0; m < 2; m++) {
        int r0 = block_row + warpM * 32 + m * 16 + lr;
        int r1 = r0 + 8;
        float no0 = (r0 < N_NODES) ? g_norm_out[r0] : 0.f;
        float no1 = (r1 < N_NODES) ? g_norm_out[r1] : 0.f;
        int sr0 = warpM * 32 + m * 16 + lr;
#pragma unroll
        for (int n = 0; n < 8; n++) {
            int col = warpN * 64 + n * 8 + lc;
            float bb0 = bs[col], bb1 = bs[col + 1];
            __half2 h0 = __floats2half2_rn(fmaxf(acc[m][n][0] + bb0, 0.f) * no0,
                                           fmaxf(acc[m][n][1] + bb1, 0.f) * no0);
            __half2 h1 = __floats2half2_rn(fmaxf(acc[m][n][2] + bb0, 0.f) * no1,
                                           fmaxf(acc[m][n][3] + bb1, 0.f) * no1);
            *(__half2*)(As + sr0 * APAD + col)       = h0;
            *(__half2*)(As + (sr0 + 8) * APAD + col) = h1;
        }
    }
    __syncthreads();

    // second MMA: z = h1 @ Wcomb; warp owns rows warp*16..+15, full K=128
    float zacc[5][4];
#pragma unroll
    for (int n = 0; n < 5; n++)
#pragma unroll
        for (int q = 0; q < 4; q++) zacc[n][q] = 0.f;

#pragma unroll
    for (int k16 = 0; k16 < 8; k16++) {
        const int kb = k16 * 16 + lc;
        const __half* ap = As + (warp * 16 + lr) * APAD;
        unsigned a0 = *(const unsigned*)(ap + kb);
        unsigned a1 = *(const unsigned*)(ap + 8 * APAD + kb);
        unsigned a2 = *(const unsigned*)(ap + kb + 8);
        unsigned a3 = *(const unsigned*)(ap + 8 * APAD + kb + 8);
#pragma unroll
        for (int n = 0; n < 5; n++) {
            const __half* bp = Wc + (n * 8 + lr) * APAD + kb;
            unsigned b0 = *(const unsigned*)(bp);
            unsigned b1 = *(const unsigned*)(bp + 8);
            asm volatile(
                "mma.sync.aligned.m16n8k16.row.col.f32.f16.f16.f32 "
                "{%0,%1,%2,%3}, {%4,%5,%6,%7}, {%8,%9}, {%0,%1,%2,%3};"
                : "+f"(zacc[n][0]), "+f"(zacc[n][1]), "+f"(zacc[n][2]), "+f"(zacc[n][3])
                : "r"(a0), "r"(a1), "r"(a2), "r"(a3), "r"(b0), "r"(b1));
        }
    }

    // epilogue 2: write z fp16 (padded) + zero cols 40..63
    int r0 = block_row + warp * 16 + lr;
    int r1 = r0 + 8;
#pragma unroll
    for (int n = 0; n < 5; n++) {
        int col = n * 8 + lc;
        if (r0 < N_NODES) {
            __half2 h = __floats2half2_rn(zacc[n][0], zacc[n][1]);
            *(__half2*)(g_zh + (size_t)r0 * ZPAD + col) = h;
        }
        if (r1 < N_NODES) {
            __half2 h = __floats2half2_rn(zacc[n][2], zacc[n][3]);
            *(__half2*)(g_zh + (size_t)r1 * ZPAD + col) = h;
        }
    }
#pragma unroll
    for (int n = 5; n < 8; n++) {
        int col = n * 8 + lc;
        if (r0 < N_NODES) *(unsigned*)(g_zh + (size_t)r0 * ZPAD + col) = 0u;
        if (r1 < N_NODES) *(unsigned*)(g_zh + (size_t)r1 * ZPAD + col) = 0u;
    }
}

// ---------------------------------------------------------------------------
// K6: gather2, 2 nodes per warp (16 lanes x uint2 over 64-half padded z row):
//   out[n, c] = norm_in[n] * sum_{s in N_in(n)} z[s, c] + bcomb[c]
__global__ void __launch_bounds__(256)
gather2_out_kernel(float* __restrict__ out) {
    int t    = blockIdx.x * blockDim.x + threadIdx.x;
    int lane = t & 31;
    int half = lane >> 4;
    int hl   = lane & 15;
    int node = (t >> 5) * 2 + half;

    int beg = 0, end = 0;
    if (node < N_NODES) { beg = g_off[node]; end = g_off[node + 1]; }

    const uint2* z2 = (const uint2*)g_zh;   // 16 uint2 per padded row

    float4 acc = make_float4(0.f, 0.f, 0.f, 0.f);
    int j = beg;
    for (; j + 4 <= end; j += 4) {
        int s0 = g_csr_src[j + 0];
        int s1 = g_csr_src[j + 1];
        int s2 = g_csr_src[j + 2];
        int s3 = g_csr_src[j + 3];
        uint2 r0 = __ldg(z2 + (size_t)s0 * 16 + hl);
        uint2 r1 = __ldg(z2 + (size_t)s1 * 16 + hl);
        uint2 r2 = __ldg(z2 + (size_t)s2 * 16 + hl);
        uint2 r3 = __ldg(z2 + (size_t)s3 * 16 + hl);
        uint2 p, q;
        *(__half2*)&p.x = __hadd2(u2h2(r0.x), u2h2(r1.x));
        *(__half2*)&p.y = __hadd2(u2h2(r0.y), u2h2(r1.y));
        *(__half2*)&q.x = __hadd2(u2h2(r2.x), u2h2(r3.x));
        *(__half2*)&q.y = __hadd2(u2h2(r2.y), u2h2(r3.y));
        acc_u2(p, acc);
        acc_u2(q, acc);
    }
    for (; j < end; j++) {
        uint2 r = __ldg(z2 + (size_t)g_csr_src[j] * 16 + hl);
        acc_u2(r, acc);
    }

    if (node < N_NODES && hl < 10) {   // 10 lanes x 4 floats = 40 output cols
        float ni = g_norm_in[node];
        float4 b = *(const float4*)(g_bcomb + hl * 4);
        float4 v = make_float4(fmaf(acc.x, ni, b.x), fmaf(acc.y, ni, b.y),
                               fmaf(acc.z, ni, b.z), fmaf(acc.w, ni, b.w));
        *(float4*)(out + (size_t)node * CDIM + hl * 4) = v;
    }
}

// ---------------------------------------------------------------------------
extern "C" void kernel_launch(void* const* d_in, const int* in_sizes, int n_in,
                              void* d_out, int out_size) {
    const float* x   = (const float*)d_in[0];
    const int*   ei  = (const int*)  d_in[1];
    const float* W1  = (const float*)d_in[2];
    const float* b1  = (const float*)d_in[3];
    const float* W2  = (const float*)d_in[4];
    const float* b2  = (const float*)d_in[5];
    const float* Wfc = (const float*)d_in[6];
    const float* bfc = (const float*)d_in[7];
    float* out = (float*)d_out;

    const int* src = ei;            // edge_index row 0
    const int* dst = ei + N_EDGES;  // edge_index row 1

    int* p_ints;
    cudaGetSymbolAddress((void**)&p_ints, g_ints);

    static bool attr_set = false;
    if (!attr_set) {
        cudaFuncSetAttribute(gemm_fused_kernel,
                             cudaFuncAttributeMaxDynamicSharedMemorySize, GEMM_SMEM);
        attr_set = true;
    }

    const int pair_blocks = ((N_NODES + 1) / 2 * 32 + 255) / 256;  // 6250
    const int node_blocks = (N_NODES + 127) / 128;                 // 782

    // zero [deg_out | deg_in | scan flags]  (cursor written by scan kernel)
    cudaMemsetAsync(p_ints, 0, (2 * N_NODES + 128) * sizeof(int));
    // K1: degrees + weight prep (independent of norms)
    deg_prep_kernel<<<K1_GRID, 256>>>(src, dst, W1, W2, Wfc, b2, bfc);
    // K2: lookback scan + norms + cursor init + x*norm_out->fp16
    scan_norm_conv_kernel<<<K2_GRID, SCAN_T>>>(x);
    // K3: CSR fill (single atomic per edge)
    fill_kernel<<<(N_EDGES + 255) / 256, 256>>>(src, dst);
    // K4 (profiled): gather1, 2 nodes/warp -> a1h
    gather1_kernel<<<pair_blocks, 256>>>();
    // K5: fused GEMM (h1 in smem) + z-GEMM (Wcomb in smem) -> zh
    gemm_fused_kernel<<<node_blocks, 256, GEMM_SMEM>>>(b1);
    // K6: gather2, 2 nodes/warp on 40-dim z rows -> out
    gather2_out_kernel<<<pair_blocks, 256>>>(out);
}